// round 1
// baseline (speedup 1.0000x reference)
#include <cuda_runtime.h>

// Problem constants (fixed by reference)
#define BATCH   1000
#define NUE_    4
#define K_      500
#define M_      500
#define N_      1000
#define NSYM_   250
#define NEDGE_  2000
#define NINFOE_ 1500
#define MAXD_   64
#define NITER_  5

// Scratch (static device allocations — no runtime alloc allowed)
__device__ unsigned char g_c[BATCH * NUE_ * N_];     // codeword bits, 4 MB
__device__ float         g_llr[BATCH * NUE_ * N_];   // channel LLRs, 16 MB
__device__ int           g_cdeg[M_];                 // check-node degree
__device__ short         g_cedge[M_ * MAXD_];        // check-node edge lists (index order)

// ---------------------------------------------------------------------------
// Build check-node CSR from cn_idx (edge order preserved => matches
// jax.ops.segment_prod accumulation order).
// ---------------------------------------------------------------------------
__global__ void setup_kernel(const int* __restrict__ cn) {
    int m = blockIdx.x * blockDim.x + threadIdx.x;
    if (m >= M_) return;
    int d = 0;
    for (int e = 0; e < NEDGE_; e++) {
        if (cn[e] == m) {
            if (d < MAXD_) g_cedge[m * MAXD_ + d] = (short)e;
            d++;
        }
    }
    g_cdeg[m] = d;
}

// ---------------------------------------------------------------------------
// Encode: copy info bits (and emit bf output), compute parity via XOR over
// the check-node info-edge lists (equivalent to round(bf@P) mod 2).
// ---------------------------------------------------------------------------
__global__ void encode_kernel(const int* __restrict__ b,
                              const int* __restrict__ vn,
                              float* __restrict__ out_bf) {
    int idx = blockIdx.x * blockDim.x + threadIdx.x;
    const int tot_info = BATCH * NUE_ * K_;
    if (idx < tot_info) {
        int w = idx / K_;
        int i = idx - w * K_;
        int bit = b[idx];
        g_c[w * N_ + i] = (unsigned char)bit;
        out_bf[idx] = (float)bit;
    } else {
        int j = idx - tot_info;
        if (j >= BATCH * NUE_ * M_) return;
        int w = j / M_;
        int m = j - w * M_;
        int d = g_cdeg[m];
        const int* bw = b + w * K_;
        int par = 0;
        for (int q = 0; q < d; q++) {
            int e = g_cedge[m * MAXD_ + q];
            if (e < NINFOE_) par ^= bw[vn[e]];
        }
        g_c[w * N_ + K_ + m] = (unsigned char)par;
    }
}

// ---------------------------------------------------------------------------
// Per-resource-element: modulate, apply channel, LMMSE detect (explicit 4x4
// complex inverse via Gauss-Jordan; A is HPD so no pivoting), max-log demap.
// One thread per r in [0, BATCH*NSYM).
// ---------------------------------------------------------------------------
__global__ __launch_bounds__(128)
void lmmse_kernel(const float* __restrict__ h_re, const float* __restrict__ h_im,
                  const float* __restrict__ n_re, const float* __restrict__ n_im,
                  const float* __restrict__ ebno) {
    int r = blockIdx.x * blockDim.x + threadIdx.x;
    if (r >= BATCH * NSYM_) return;

    const float no  = 1.0f / (exp10f(ebno[0] * 0.1f) * 2.0f);  // BPS*RATE = 2
    const int bidx = r / NSYM_;
    const int s    = r - bidx * NSYM_;
    const float is2 = 0.70710678118654752440f;  // 1/sqrt(2)
    const float s10 = 0.31622776601683794f;     // 1/sqrt(10)

    float hr[4][4], hi[4][4];
#pragma unroll
    for (int i = 0; i < 4; i++)
#pragma unroll
        for (int j = 0; j < 4; j++) {
            hr[i][j] = h_re[(r * 4 + i) * 4 + j] * is2;
            hi[i][j] = h_im[(r * 4 + i) * 4 + j] * is2;
        }

    // Modulate the 4 UEs' symbols for this RE
    float xr[4], xi[4];
#pragma unroll
    for (int j = 0; j < 4; j++) {
        const unsigned char* cb = &g_c[(bidx * NUE_ + j) * N_ + s * 4];
        int b0 = cb[0], b1 = cb[1], b2 = cb[2], b3 = cb[3];
        xr[j] = (float)((1 - 2 * b0) * (1 + 2 * b2)) * s10;
        xi[j] = (float)((1 - 2 * b1) * (1 + 2 * b3)) * s10;
    }

    // y = H x + w
    const float ns = sqrtf(no * 0.5f);
    float yr[4], yi[4];
#pragma unroll
    for (int i = 0; i < 4; i++) {
        float ar = n_re[r * 4 + i] * ns;
        float ai = n_im[r * 4 + i] * ns;
#pragma unroll
        for (int j = 0; j < 4; j++) {
            ar += hr[i][j] * xr[j] - hi[i][j] * xi[j];
            ai += hr[i][j] * xi[j] + hi[i][j] * xr[j];
        }
        yr[i] = ar; yi[i] = ai;
    }

    // A = H H^H + no*I ; B = A^{-1} via Gauss-Jordan (complex)
    float Ar[4][4], Ai[4][4], Br[4][4], Bi[4][4];
#pragma unroll
    for (int i = 0; i < 4; i++)
#pragma unroll
        for (int k = 0; k < 4; k++) {
            float ar = (i == k) ? no : 0.f;
            float ai = 0.f;
#pragma unroll
            for (int j = 0; j < 4; j++) {
                ar += hr[i][j] * hr[k][j] + hi[i][j] * hi[k][j];
                ai += hi[i][j] * hr[k][j] - hr[i][j] * hi[k][j];
            }
            Ar[i][k] = ar; Ai[i][k] = ai;
            Br[i][k] = (i == k) ? 1.f : 0.f; Bi[i][k] = 0.f;
        }
#pragma unroll
    for (int k = 0; k < 4; k++) {
        float pr = Ar[k][k], pi = Ai[k][k];
        float inv = 1.0f / (pr * pr + pi * pi);
        float qr = pr * inv, qi = -pi * inv;
#pragma unroll
        for (int c = 0; c < 4; c++) {
            float tr = Ar[k][c], ti = Ai[k][c];
            Ar[k][c] = tr * qr - ti * qi; Ai[k][c] = tr * qi + ti * qr;
            tr = Br[k][c]; ti = Bi[k][c];
            Br[k][c] = tr * qr - ti * qi; Bi[k][c] = tr * qi + ti * qr;
        }
#pragma unroll
        for (int i = 0; i < 4; i++) {
            if (i == k) continue;
            float fr = Ar[i][k], fi = Ai[i][k];
#pragma unroll
            for (int c = 0; c < 4; c++) {
                float kr = Ar[k][c], ki = Ai[k][c];
                Ar[i][c] -= fr * kr - fi * ki;
                Ai[i][c] -= fr * ki + fi * kr;
                kr = Br[k][c]; ki = Bi[k][c];
                Br[i][c] -= fr * kr - fi * ki;
                Bi[i][c] -= fr * ki + fi * kr;
            }
        }
    }

    // z = A^{-1} y
    float zr[4], zi[4];
#pragma unroll
    for (int i = 0; i < 4; i++) {
        float ar = 0.f, ai = 0.f;
#pragma unroll
        for (int c = 0; c < 4; c++) {
            ar += Br[i][c] * yr[c] - Bi[i][c] * yi[c];
            ai += Br[i][c] * yi[c] + Bi[i][c] * yr[c];
        }
        zr[i] = ar; zi[i] = ai;
    }

    float* llr_base = &g_llr[(bidx * NUE_) * N_ + s * 4];
#pragma unroll
    for (int j = 0; j < 4; j++) {
        // x_raw_j = h_j^H z ; d_j = Re(h_j^H A^{-1} h_j)
        float sr = 0.f, si = 0.f, d = 0.f;
#pragma unroll
        for (int i = 0; i < 4; i++) {
            sr += hr[i][j] * zr[i] + hi[i][j] * zi[i];
            si += hr[i][j] * zi[i] - hi[i][j] * zr[i];
            float ur = 0.f, ui = 0.f;
#pragma unroll
            for (int c = 0; c < 4; c++) {
                ur += Br[i][c] * hr[c][j] - Bi[i][c] * hi[c][j];
                ui += Br[i][c] * hi[c][j] + Bi[i][c] * hr[c][j];
            }
            d += hr[i][j] * ur + hi[i][j] * ui;
        }
        float xhr = sr / d, xhi = si / d;
        float noeff = fmaxf(1.0f / d - 1.0f, 1e-12f);

        float met[16];
#pragma unroll
        for (int p = 0; p < 16; p++) {
            int b0 = (p >> 3) & 1, b1 = (p >> 2) & 1, b2 = (p >> 1) & 1, b3 = p & 1;
            float pr  = (float)((1 - 2 * b0) * (1 + 2 * b2)) * s10;
            float pim = (float)((1 - 2 * b1) * (1 + 2 * b3)) * s10;
            float dr = xhr - pr, di = xhi - pim;
            met[p] = -(dr * dr + di * di) / noeff;
        }
#pragma unroll
        for (int kbit = 0; kbit < 4; kbit++) {
            float m0 = -1e30f, m1 = -1e30f;
#pragma unroll
            for (int p = 0; p < 16; p++) {
                if ((p >> (3 - kbit)) & 1) m1 = fmaxf(m1, met[p]);
                else                       m0 = fmaxf(m0, met[p]);
            }
            llr_base[j * N_ + kbit] = m0 - m1;
        }
    }
}

// ---------------------------------------------------------------------------
// LDPC decoder: one block per codeword, everything in shared memory.
// Variable-side structure is analytic: info var i owns edges 3i..3i+2,
// parity var K+m owns edge 1500+m.
// ---------------------------------------------------------------------------
__global__ __launch_bounds__(256)
void decode_kernel(const int* __restrict__ cn, float* __restrict__ out_bhat) {
    __shared__ float sL[N_];
    __shared__ float sC[NEDGE_];
    __shared__ float sV[N_];
    __shared__ float sT[NEDGE_];
    __shared__ float sP[M_];
    __shared__ short scn[NEDGE_];

    const int w = blockIdx.x;
    const int t = threadIdx.x;
    const float* Lg = g_llr + (size_t)w * N_;

    for (int n = t; n < N_; n += blockDim.x) sL[n] = Lg[n];
    for (int e = t; e < NEDGE_; e += blockDim.x) { sC[e] = 0.f; scn[e] = (short)cn[e]; }
    __syncthreads();

    for (int it = 0; it < NITER_; it++) {
        // variable-node totals
        for (int n = t; n < N_; n += blockDim.x) {
            float v = sL[n];
            if (n < K_) v += sC[3 * n] + sC[3 * n + 1] + sC[3 * n + 2];
            else        v += sC[NINFOE_ + (n - K_)];
            sV[n] = v;
        }
        __syncthreads();
        // v->c messages -> tanh
        for (int e = t; e < NEDGE_; e += blockDim.x) {
            int vnode = (e < NINFOE_) ? (e / 3) : (K_ + (e - NINFOE_));
            float x = (sV[vnode] - sC[e]) * 0.5f;
            x = fminf(fmaxf(x, -9.9f), 9.9f);
            float th = tanhf(x);
            th = (th >= 0.f) ? fmaxf(th, 1e-7f) : fminf(th, -1e-7f);
            sT[e] = th;
        }
        __syncthreads();
        // check-node products (edge-index order)
        for (int m = t; m < M_; m += blockDim.x) {
            int d = g_cdeg[m];
            float p = 1.f;
            for (int q = 0; q < d; q++) p *= sT[g_cedge[m * MAXD_ + q]];
            sP[m] = p;
        }
        __syncthreads();
        // c->v messages
        for (int e = t; e < NEDGE_; e += blockDim.x) {
            float ratio = sP[scn[e]] / sT[e];
            ratio = fminf(fmaxf(ratio, -0.999999f), 0.999999f);
            sC[e] = 2.f * atanhf(ratio);
        }
        __syncthreads();
    }

    // final hard decision on info bits
    for (int n = t; n < K_; n += blockDim.x) {
        float v = sL[n] + sC[3 * n] + sC[3 * n + 1] + sC[3 * n + 2];
        out_bhat[(size_t)w * K_ + n] = (v < 0.f) ? 1.0f : 0.0f;
    }
}

// ---------------------------------------------------------------------------
extern "C" void kernel_launch(void* const* d_in, const int* in_sizes, int n_in,
                              void* d_out, int out_size) {
    // Expected order: batch_size, ebno_db, b, P, cn_idx, vn_idx, h_re, h_im,
    // noise_re, noise_im. Tolerate a missing leading scalar (shift).
    int shift = 10 - n_in;
    const float* ebno = (const float*)d_in[1 - shift];
    const int*   b    = (const int*)  d_in[2 - shift];
    const int*   cn   = (const int*)  d_in[4 - shift];
    const int*   vn   = (const int*)  d_in[5 - shift];
    const float* h_re = (const float*)d_in[6 - shift];
    const float* h_im = (const float*)d_in[7 - shift];
    const float* n_re = (const float*)d_in[8 - shift];
    const float* n_im = (const float*)d_in[9 - shift];

    float* out_bf = (float*)d_out;                       // (batch, NUE, K)
    float* out_bh = (float*)d_out + BATCH * NUE_ * K_;   // (batch, NUE, K)

    setup_kernel<<<2, 256>>>(cn);

    const int tot = BATCH * NUE_ * (K_ + M_);
    encode_kernel<<<(tot + 255) / 256, 256>>>(b, vn, out_bf);

    const int nr = BATCH * NSYM_;
    lmmse_kernel<<<(nr + 127) / 128, 128>>>(h_re, h_im, n_re, n_im, ebno);

    decode_kernel<<<BATCH * NUE_, 256>>>(cn, out_bh);
}

// round 2
// speedup vs baseline: 2.1546x; 2.1546x over previous
#include <cuda_runtime.h>

// Problem constants (fixed by reference)
#define BATCH   1000
#define NUE_    4
#define K_      500
#define M_      500
#define N_      1000
#define NSYM_   250
#define NEDGE_  2000
#define NINFOE_ 1500
#define NITER_  5

// Static scratch (no runtime allocation allowed)
__device__ unsigned char g_c[BATCH * NUE_ * N_];     // codeword bits
__device__ float         g_llr[BATCH * NUE_ * N_];   // channel LLRs
__device__ short         g_eoff[M_ + 1];             // info-edge CSR offsets per check
__device__ short         g_elist[NINFOE_];           // info-edge ids, ascending per check
__device__ int           g_fill[M_];                 // placement cursors

// ---------------------------------------------------------------------------
// Setup: build per-check CSR of info edges (ascending edge order to match
// jax segment_prod accumulation order).
// ---------------------------------------------------------------------------
__global__ void setup_count_kernel(const int* __restrict__ cn) {
    __shared__ int cnt[M_];
    int t = threadIdx.x;
    for (int m = t; m < M_; m += blockDim.x) cnt[m] = 0;
    __syncthreads();
    for (int e = t; e < NINFOE_; e += blockDim.x) atomicAdd(&cnt[cn[e]], 1);
    __syncthreads();
    if (t == 0) {
        int run = 0;
        for (int m = 0; m < M_; m++) { g_eoff[m] = (short)run; run += cnt[m]; }
        g_eoff[M_] = (short)run;
    }
    for (int m = t; m < M_; m += blockDim.x) g_fill[m] = 0;
}

__global__ void setup_place_kernel(const int* __restrict__ cn) {
    int e = blockIdx.x * blockDim.x + threadIdx.x;
    if (e >= NINFOE_) return;
    int c = cn[e];
    int slot = atomicAdd(&g_fill[c], 1);
    g_elist[(int)g_eoff[c] + slot] = (short)e;
}

__global__ void setup_sort_kernel() {
    int m = blockIdx.x * blockDim.x + threadIdx.x;
    if (m >= M_) return;
    int o0 = g_eoff[m], o1 = g_eoff[m + 1];
    for (int i = o0 + 1; i < o1; i++) {
        short v = g_elist[i];
        int j = i - 1;
        while (j >= o0 && g_elist[j] > v) { g_elist[j + 1] = g_elist[j]; j--; }
        g_elist[j + 1] = v;
    }
}

// ---------------------------------------------------------------------------
// Encode: info var of edge e is e/3 (vn structure is analytic), parity =
// XOR over each check's info-edge rows.
// ---------------------------------------------------------------------------
__global__ void encode_kernel(const int* __restrict__ b, float* __restrict__ out_bf) {
    int idx = blockIdx.x * blockDim.x + threadIdx.x;
    const int tot_info = BATCH * NUE_ * K_;
    if (idx < tot_info) {
        int w = idx / K_;
        int i = idx - w * K_;
        int bit = b[idx];
        g_c[w * N_ + i] = (unsigned char)bit;
        out_bf[idx] = (float)bit;
    } else {
        int j = idx - tot_info;
        if (j >= BATCH * NUE_ * M_) return;
        int w = j / M_;
        int m = j - w * M_;
        int o0 = g_eoff[m], o1 = g_eoff[m + 1];
        const int* bw = b + w * K_;
        int par = 0;
        for (int q = o0; q < o1; q++) {
            int e = g_elist[q];
            par ^= bw[e / 3];
        }
        g_c[w * N_ + K_ + m] = (unsigned char)par;
    }
}

// ---------------------------------------------------------------------------
// LMMSE: modulate, channel, Cholesky-based detect (A = HH^H+no*I is HPD):
//   d_j = ||L^{-1} h_j||^2,  z = A^{-1} y via fwd/back solve.
// ---------------------------------------------------------------------------
__global__ __launch_bounds__(128)
void lmmse_kernel(const float4* __restrict__ hre4, const float4* __restrict__ him4,
                  const float4* __restrict__ nre4, const float4* __restrict__ nim4,
                  const float* __restrict__ ebno) {
    int r = blockIdx.x * blockDim.x + threadIdx.x;
    if (r >= BATCH * NSYM_) return;

    const float no  = 1.0f / (exp10f(ebno[0] * 0.1f) * 2.0f);  // BPS*RATE = 2
    const int bidx = r / NSYM_;
    const int s    = r - bidx * NSYM_;
    const float is2 = 0.70710678118654752440f;  // 1/sqrt(2)
    const float s10 = 0.31622776601683794f;     // 1/sqrt(10)

    float hr[4][4], hi[4][4];
#pragma unroll
    for (int i = 0; i < 4; i++) {
        float4 vr = hre4[r * 4 + i];
        float4 vi = him4[r * 4 + i];
        hr[i][0] = vr.x * is2; hr[i][1] = vr.y * is2; hr[i][2] = vr.z * is2; hr[i][3] = vr.w * is2;
        hi[i][0] = vi.x * is2; hi[i][1] = vi.y * is2; hi[i][2] = vi.z * is2; hi[i][3] = vi.w * is2;
    }

    // Modulate the 4 UEs' symbols
    float xr[4], xi[4];
#pragma unroll
    for (int j = 0; j < 4; j++) {
        const unsigned char* cb = &g_c[(bidx * NUE_ + j) * N_ + s * 4];
        int b0 = cb[0], b1 = cb[1], b2 = cb[2], b3 = cb[3];
        xr[j] = (float)((1 - 2 * b0) * (1 + 2 * b2)) * s10;
        xi[j] = (float)((1 - 2 * b1) * (1 + 2 * b3)) * s10;
    }

    // y = H x + w
    const float ns = sqrtf(no * 0.5f);
    float4 wr4 = nre4[r], wi4 = nim4[r];
    float yr[4] = {wr4.x * ns, wr4.y * ns, wr4.z * ns, wr4.w * ns};
    float yi[4] = {wi4.x * ns, wi4.y * ns, wi4.z * ns, wi4.w * ns};
#pragma unroll
    for (int i = 0; i < 4; i++)
#pragma unroll
        for (int j = 0; j < 4; j++) {
            yr[i] += hr[i][j] * xr[j] - hi[i][j] * xi[j];
            yi[i] += hr[i][j] * xi[j] + hi[i][j] * xr[j];
        }

    // A (lower triangle), A = H H^H + no*I
    float Ar[4][4], Ai[4][4];
#pragma unroll
    for (int i = 0; i < 4; i++)
#pragma unroll
        for (int k = 0; k < 4; k++) {
            if (k > i) continue;
            float ar = (i == k) ? no : 0.f;
            float ai = 0.f;
#pragma unroll
            for (int j = 0; j < 4; j++) {
                ar += hr[i][j] * hr[k][j] + hi[i][j] * hi[k][j];
                ai += hi[i][j] * hr[k][j] - hr[i][j] * hi[k][j];
            }
            Ar[i][k] = ar; Ai[i][k] = ai;
        }

    // In-place complex Cholesky: A = L L^H, rk[k] = 1/L[k][k]
    float rk[4];
#pragma unroll
    for (int k = 0; k < 4; k++) {
        float v = Ar[k][k];
#pragma unroll
        for (int j = 0; j < 4; j++)
            if (j < k) v -= Ar[k][j] * Ar[k][j] + Ai[k][j] * Ai[k][j];
        float lkk = sqrtf(v);
        float inv = 1.0f / lkk;
        rk[k] = inv;
#pragma unroll
        for (int i = 0; i < 4; i++) {
            if (i <= k) continue;
            float cr = Ar[i][k], ci = Ai[i][k];
#pragma unroll
            for (int j = 0; j < 4; j++)
                if (j < k) {
                    cr -= Ar[i][j] * Ar[k][j] + Ai[i][j] * Ai[k][j];
                    ci -= Ai[i][j] * Ar[k][j] - Ar[i][j] * Ai[k][j];
                }
            Ar[i][k] = cr * inv; Ai[i][k] = ci * inv;
        }
    }

    // Forward solve L u = y
    float ur[4], ui[4];
#pragma unroll
    for (int i = 0; i < 4; i++) {
        float ar = yr[i], ai = yi[i];
#pragma unroll
        for (int j = 0; j < 4; j++)
            if (j < i) {
                ar -= Ar[i][j] * ur[j] - Ai[i][j] * ui[j];
                ai -= Ar[i][j] * ui[j] + Ai[i][j] * ur[j];
            }
        ur[i] = ar * rk[i]; ui[i] = ai * rk[i];
    }
    // Back solve L^H z = u
    float zr[4], zi[4];
#pragma unroll
    for (int ii = 0; ii < 4; ii++) {
        int i = 3 - ii;
        float ar = ur[i], ai = ui[i];
#pragma unroll
        for (int j = 0; j < 4; j++)
            if (j > i) {
                ar -= Ar[j][i] * zr[j] + Ai[j][i] * zi[j];
                ai -= Ar[j][i] * zi[j] - Ai[j][i] * zr[j];
            }
        zr[i] = ar * rk[i]; zi[i] = ai * rk[i];
    }

    float* llr_base = &g_llr[(size_t)(bidx * NUE_) * N_ + s * 4];
#pragma unroll
    for (int c = 0; c < 4; c++) {
        // g = L^{-1} h_col(c); d = ||g||^2
        float gr[4], gi[4], d = 0.f;
#pragma unroll
        for (int i = 0; i < 4; i++) {
            float ar = hr[i][c], ai = hi[i][c];
#pragma unroll
            for (int j = 0; j < 4; j++)
                if (j < i) {
                    ar -= Ar[i][j] * gr[j] - Ai[i][j] * gi[j];
                    ai -= Ar[i][j] * gi[j] + Ai[i][j] * gr[j];
                }
            gr[i] = ar * rk[i]; gi[i] = ai * rk[i];
            d += gr[i] * gr[i] + gi[i] * gi[i];
        }
        // x_raw = h_c^H z
        float sr = 0.f, si = 0.f;
#pragma unroll
        for (int i = 0; i < 4; i++) {
            sr += hr[i][c] * zr[i] + hi[i][c] * zi[i];
            si += hr[i][c] * zi[i] - hi[i][c] * zr[i];
        }
        float invd = 1.0f / d;
        float xhr = sr * invd, xhi = si * invd;
        float noeff = fmaxf(invd - 1.0f, 1e-12f);
        float inoe = 1.0f / noeff;

        float u0[4] = {-1e30f, -1e30f, -1e30f, -1e30f};
        float u1[4] = {-1e30f, -1e30f, -1e30f, -1e30f};
#pragma unroll
        for (int p = 0; p < 16; p++) {
            int b0 = (p >> 3) & 1, b1 = (p >> 2) & 1, b2 = (p >> 1) & 1, b3 = p & 1;
            float pr  = (float)((1 - 2 * b0) * (1 + 2 * b2)) * s10;
            float pim = (float)((1 - 2 * b1) * (1 + 2 * b3)) * s10;
            float dr = xhr - pr, di = xhi - pim;
            float met = -(dr * dr + di * di);
            if (b0) u1[0] = fmaxf(u1[0], met); else u0[0] = fmaxf(u0[0], met);
            if (b1) u1[1] = fmaxf(u1[1], met); else u0[1] = fmaxf(u0[1], met);
            if (b2) u1[2] = fmaxf(u1[2], met); else u0[2] = fmaxf(u0[2], met);
            if (b3) u1[3] = fmaxf(u1[3], met); else u0[3] = fmaxf(u0[3], met);
        }
#pragma unroll
        for (int kbit = 0; kbit < 4; kbit++)
            llr_base[c * N_ + kbit] = (u0[kbit] - u1[kbit]) * inoe;
    }
}

// ---------------------------------------------------------------------------
// Decoder: one block per codeword. Fast transcendentals via MUFU:
//   tanh(x) = 1 - 2/(exp(2x)+1),   2*atanh(r) = log((1+r)/(1-r)).
// Parity vars (deg-1): tanh loop-invariant; their c2v is never consumed.
// ---------------------------------------------------------------------------
__device__ __forceinline__ float tanh_clip_half(float x) {
    x = fminf(fmaxf(x, -9.9f), 9.9f);
    float e = __expf(2.0f * x);
    float th = 1.0f - __fdividef(2.0f, e + 1.0f);
    return (th >= 0.f) ? fmaxf(th, 1e-7f) : fminf(th, -1e-7f);
}

__global__ __launch_bounds__(256)
void decode_kernel(float* __restrict__ out_bhat) {
    __shared__ float sL[N_];
    __shared__ float sC[NINFOE_];
    __shared__ float sT[NEDGE_];

    const int w = blockIdx.x;
    const int t = threadIdx.x;
    const float* Lg = g_llr + (size_t)w * N_;

    for (int n = t; n < N_; n += 256) sL[n] = Lg[n];
    for (int e = t; e < NINFOE_; e += 256) sC[e] = 0.f;
    __syncthreads();
    // parity-edge tanh is loop-invariant (m_vc = Lch always)
    for (int m = t; m < M_; m += 256)
        sT[NINFOE_ + m] = tanh_clip_half(sL[K_ + m] * 0.5f);

    for (int it = 0; it < NITER_; it++) {
        // info variables: vtot + 3 v->c messages -> tanh
        for (int n = t; n < K_; n += 256) {
            float c0 = sC[3 * n], c1 = sC[3 * n + 1], c2 = sC[3 * n + 2];
            float vt = sL[n] + c0 + c1 + c2;
            sT[3 * n    ] = tanh_clip_half((vt - c0) * 0.5f);
            sT[3 * n + 1] = tanh_clip_half((vt - c1) * 0.5f);
            sT[3 * n + 2] = tanh_clip_half((vt - c2) * 0.5f);
        }
        __syncthreads();
        // checks: product in ascending edge order (parity edge last), then c2v
        for (int m = t; m < M_; m += 256) {
            int o0 = g_eoff[m], o1 = g_eoff[m + 1];
            float p = 1.f;
            for (int q = o0; q < o1; q++) p *= sT[g_elist[q]];
            p *= sT[NINFOE_ + m];
            for (int q = o0; q < o1; q++) {
                int e = g_elist[q];
                float rr = __fdividef(p, sT[e]);
                rr = fminf(fmaxf(rr, -0.999999f), 0.999999f);
                sC[e] = __logf(__fdividef(1.0f + rr, 1.0f - rr));
            }
        }
        __syncthreads();
    }

    float* ob = out_bhat + (size_t)w * K_;
    for (int n = t; n < K_; n += 256) {
        float v = sL[n] + sC[3 * n] + sC[3 * n + 1] + sC[3 * n + 2];
        ob[n] = (v < 0.f) ? 1.0f : 0.0f;
    }
}

// ---------------------------------------------------------------------------
extern "C" void kernel_launch(void* const* d_in, const int* in_sizes, int n_in,
                              void* d_out, int out_size) {
    int shift = 10 - n_in;
    const float* ebno = (const float*)d_in[1 - shift];
    const int*   b    = (const int*)  d_in[2 - shift];
    const int*   cn   = (const int*)  d_in[4 - shift];
    const float* h_re = (const float*)d_in[6 - shift];
    const float* h_im = (const float*)d_in[7 - shift];
    const float* n_re = (const float*)d_in[8 - shift];
    const float* n_im = (const float*)d_in[9 - shift];

    float* out_bf = (float*)d_out;                       // (batch, NUE, K)
    float* out_bh = (float*)d_out + BATCH * NUE_ * K_;   // (batch, NUE, K)

    setup_count_kernel<<<1, 512>>>(cn);
    setup_place_kernel<<<(NINFOE_ + 255) / 256, 256>>>(cn);
    setup_sort_kernel<<<(M_ + 255) / 256, 256>>>();

    const int tot = BATCH * NUE_ * N_;
    encode_kernel<<<(tot + 255) / 256, 256>>>(b, out_bf);

    const int nr = BATCH * NSYM_;
    lmmse_kernel<<<(nr + 127) / 128, 128>>>((const float4*)h_re, (const float4*)h_im,
                                            (const float4*)n_re, (const float4*)n_im, ebno);

    decode_kernel<<<BATCH * NUE_, 256>>>(out_bh);
}

// round 3
// speedup vs baseline: 2.2193x; 1.0300x over previous
#include <cuda_runtime.h>

// Problem constants (fixed by reference)
#define BATCH   1000
#define NUE_    4
#define K_      500
#define M_      500
#define N_      1000
#define NSYM_   250
#define NEDGE_  2000
#define NINFOE_ 1500
#define NITER_  5

// Static scratch (no runtime allocation allowed)
__device__ unsigned char g_c[BATCH * NUE_ * N_];     // codeword bits
__device__ float         g_llr[BATCH * NUE_ * N_];   // channel LLRs
__device__ short         g_eoff[M_ + 1];             // info-edge CSR offsets per check
__device__ short         g_elist[NINFOE_];           // info-edge ids, ascending per check
__device__ int           g_fill[M_];                 // placement cursors

// ---------------------------------------------------------------------------
// Accurate-but-fast transcendentals.
// tanh: Pade [3/3] for |x|<1 (rel err <= 3e-7), exp form for |x|>=1 (t>=0.76).
// 2*atanh: Taylor through r^7 for |r|<0.25, log form otherwise.
// ---------------------------------------------------------------------------
__device__ __forceinline__ float tanh_clip_half(float x) {
    x = fminf(fmaxf(x, -9.9f), 9.9f);
    float ax = fabsf(x);
    float x2 = x * x;
    float num = x * fmaf(x2, fmaf(x2, 1.0f, 105.0f), 945.0f);
    float den = fmaf(x2, fmaf(x2, 15.0f, 420.0f), 945.0f);
    float tp  = __fdividef(num, den);
    float e   = __expf(2.0f * ax);
    float te  = copysignf(1.0f - __fdividef(2.0f, e + 1.0f), x);
    float t   = (ax < 1.0f) ? tp : te;
    return (t >= 0.f) ? fmaxf(t, 1e-7f) : fminf(t, -1e-7f);
}

__device__ __forceinline__ float atanh2_acc(float r) {
    r = fminf(fmaxf(r, -0.999999f), 0.999999f);
    float r2 = r * r;
    // 2r + (2/3)r^3 + (2/5)r^5 + (2/7)r^7
    float poly = r * fmaf(r2, fmaf(r2, fmaf(r2, 0.28571428571f, 0.4f), 0.66666666667f), 2.0f);
    float q  = __fdividef(1.0f + r, 1.0f - r);
    float lg = __logf(q);
    return (fabsf(r) < 0.25f) ? poly : lg;
}

// ---------------------------------------------------------------------------
// Setup: build per-check CSR of info edges (ascending edge order to match
// jax segment_prod accumulation order).
// ---------------------------------------------------------------------------
__global__ void setup_count_kernel(const int* __restrict__ cn) {
    __shared__ int cnt[M_];
    int t = threadIdx.x;
    for (int m = t; m < M_; m += blockDim.x) cnt[m] = 0;
    __syncthreads();
    for (int e = t; e < NINFOE_; e += blockDim.x) atomicAdd(&cnt[cn[e]], 1);
    __syncthreads();
    if (t == 0) {
        int run = 0;
        for (int m = 0; m < M_; m++) { g_eoff[m] = (short)run; run += cnt[m]; }
        g_eoff[M_] = (short)run;
    }
    for (int m = t; m < M_; m += blockDim.x) g_fill[m] = 0;
}

__global__ void setup_place_kernel(const int* __restrict__ cn) {
    int e = blockIdx.x * blockDim.x + threadIdx.x;
    if (e >= NINFOE_) return;
    int c = cn[e];
    int slot = atomicAdd(&g_fill[c], 1);
    g_elist[(int)g_eoff[c] + slot] = (short)e;
}

__global__ void setup_sort_kernel() {
    int m = blockIdx.x * blockDim.x + threadIdx.x;
    if (m >= M_) return;
    int o0 = g_eoff[m], o1 = g_eoff[m + 1];
    for (int i = o0 + 1; i < o1; i++) {
        short v = g_elist[i];
        int j = i - 1;
        while (j >= o0 && g_elist[j] > v) { g_elist[j + 1] = g_elist[j]; j--; }
        g_elist[j + 1] = v;
    }
}

// ---------------------------------------------------------------------------
// Encode: one block per codeword, info bits staged in shared. Parity = XOR
// over each check's info-edge rows (info var of edge e is e/3).
// ---------------------------------------------------------------------------
__global__ __launch_bounds__(256)
void encode_kernel(const int* __restrict__ b, float* __restrict__ out_bf) {
    __shared__ int sb[K_];
    const int w = blockIdx.x;
    const int t = threadIdx.x;
    const int* bw = b + (size_t)w * K_;
    unsigned char* cw = g_c + (size_t)w * N_;
    float* of = out_bf + (size_t)w * K_;

    for (int i = t; i < K_; i += 256) {
        int bit = bw[i];
        sb[i] = bit;
        cw[i] = (unsigned char)bit;
        of[i] = (float)bit;
    }
    __syncthreads();
    for (int m = t; m < M_; m += 256) {
        int o0 = g_eoff[m], o1 = g_eoff[m + 1];
        int par = 0;
        for (int q = o0; q < o1; q++) par ^= sb[g_elist[q] / 3];
        cw[K_ + m] = (unsigned char)par;
    }
}

// ---------------------------------------------------------------------------
// LMMSE: modulate, channel, Cholesky-based detect (A = HH^H+no*I is HPD):
//   d_j = ||L^{-1} h_j||^2,  z = A^{-1} y via fwd/back solve.
// ---------------------------------------------------------------------------
__global__ __launch_bounds__(128)
void lmmse_kernel(const float4* __restrict__ hre4, const float4* __restrict__ him4,
                  const float4* __restrict__ nre4, const float4* __restrict__ nim4,
                  const float* __restrict__ ebno) {
    int r = blockIdx.x * blockDim.x + threadIdx.x;
    if (r >= BATCH * NSYM_) return;

    const float no  = 1.0f / (exp10f(ebno[0] * 0.1f) * 2.0f);  // BPS*RATE = 2
    const int bidx = r / NSYM_;
    const int s    = r - bidx * NSYM_;
    const float is2 = 0.70710678118654752440f;  // 1/sqrt(2)
    const float s10 = 0.31622776601683794f;     // 1/sqrt(10)

    float hr[4][4], hi[4][4];
#pragma unroll
    for (int i = 0; i < 4; i++) {
        float4 vr = hre4[r * 4 + i];
        float4 vi = him4[r * 4 + i];
        hr[i][0] = vr.x * is2; hr[i][1] = vr.y * is2; hr[i][2] = vr.z * is2; hr[i][3] = vr.w * is2;
        hi[i][0] = vi.x * is2; hi[i][1] = vi.y * is2; hi[i][2] = vi.z * is2; hi[i][3] = vi.w * is2;
    }

    // Modulate the 4 UEs' symbols (vectorized bit load)
    float xr[4], xi[4];
#pragma unroll
    for (int j = 0; j < 4; j++) {
        uchar4 cb = *(const uchar4*)&g_c[(size_t)(bidx * NUE_ + j) * N_ + s * 4];
        xr[j] = (float)((1 - 2 * (int)cb.x) * (1 + 2 * (int)cb.z)) * s10;
        xi[j] = (float)((1 - 2 * (int)cb.y) * (1 + 2 * (int)cb.w)) * s10;
    }

    // y = H x + w
    const float ns = sqrtf(no * 0.5f);
    float4 wr4 = nre4[r], wi4 = nim4[r];
    float yr[4] = {wr4.x * ns, wr4.y * ns, wr4.z * ns, wr4.w * ns};
    float yi[4] = {wi4.x * ns, wi4.y * ns, wi4.z * ns, wi4.w * ns};
#pragma unroll
    for (int i = 0; i < 4; i++)
#pragma unroll
        for (int j = 0; j < 4; j++) {
            yr[i] += hr[i][j] * xr[j] - hi[i][j] * xi[j];
            yi[i] += hr[i][j] * xi[j] + hi[i][j] * xr[j];
        }

    // A (lower triangle), A = H H^H + no*I
    float Ar[4][4], Ai[4][4];
#pragma unroll
    for (int i = 0; i < 4; i++)
#pragma unroll
        for (int k = 0; k < 4; k++) {
            if (k > i) continue;
            float ar = (i == k) ? no : 0.f;
            float ai = 0.f;
#pragma unroll
            for (int j = 0; j < 4; j++) {
                ar += hr[i][j] * hr[k][j] + hi[i][j] * hi[k][j];
                ai += hi[i][j] * hr[k][j] - hr[i][j] * hi[k][j];
            }
            Ar[i][k] = ar; Ai[i][k] = ai;
        }

    // In-place complex Cholesky: A = L L^H, rk[k] = 1/L[k][k]
    float rk[4];
#pragma unroll
    for (int k = 0; k < 4; k++) {
        float v = Ar[k][k];
#pragma unroll
        for (int j = 0; j < 4; j++)
            if (j < k) v -= Ar[k][j] * Ar[k][j] + Ai[k][j] * Ai[k][j];
        float inv = rsqrtf(v);
        rk[k] = inv;
#pragma unroll
        for (int i = 0; i < 4; i++) {
            if (i <= k) continue;
            float cr = Ar[i][k], ci = Ai[i][k];
#pragma unroll
            for (int j = 0; j < 4; j++)
                if (j < k) {
                    cr -= Ar[i][j] * Ar[k][j] + Ai[i][j] * Ai[k][j];
                    ci -= Ai[i][j] * Ar[k][j] - Ar[i][j] * Ai[k][j];
                }
            Ar[i][k] = cr * inv; Ai[i][k] = ci * inv;
        }
    }

    // Forward solve L u = y
    float ur[4], ui[4];
#pragma unroll
    for (int i = 0; i < 4; i++) {
        float ar = yr[i], ai = yi[i];
#pragma unroll
        for (int j = 0; j < 4; j++)
            if (j < i) {
                ar -= Ar[i][j] * ur[j] - Ai[i][j] * ui[j];
                ai -= Ar[i][j] * ui[j] + Ai[i][j] * ur[j];
            }
        ur[i] = ar * rk[i]; ui[i] = ai * rk[i];
    }
    // Back solve L^H z = u
    float zr[4], zi[4];
#pragma unroll
    for (int ii = 0; ii < 4; ii++) {
        int i = 3 - ii;
        float ar = ur[i], ai = ui[i];
#pragma unroll
        for (int j = 0; j < 4; j++)
            if (j > i) {
                ar -= Ar[j][i] * zr[j] + Ai[j][i] * zi[j];
                ai -= Ar[j][i] * zi[j] - Ai[j][i] * zr[j];
            }
        zr[i] = ar * rk[i]; zi[i] = ai * rk[i];
    }

#pragma unroll
    for (int c = 0; c < 4; c++) {
        // g = L^{-1} h_col(c); d = ||g||^2
        float gr[4], gi[4], d = 0.f;
#pragma unroll
        for (int i = 0; i < 4; i++) {
            float ar = hr[i][c], ai = hi[i][c];
#pragma unroll
            for (int j = 0; j < 4; j++)
                if (j < i) {
                    ar -= Ar[i][j] * gr[j] - Ai[i][j] * gi[j];
                    ai -= Ar[i][j] * gi[j] + Ai[i][j] * gr[j];
                }
            gr[i] = ar * rk[i]; gi[i] = ai * rk[i];
            d += gr[i] * gr[i] + gi[i] * gi[i];
        }
        // x_raw = h_c^H z
        float sr = 0.f, si = 0.f;
#pragma unroll
        for (int i = 0; i < 4; i++) {
            sr += hr[i][c] * zr[i] + hi[i][c] * zi[i];
            si += hr[i][c] * zi[i] - hi[i][c] * zr[i];
        }
        float invd = 1.0f / d;
        float xhr = sr * invd, xhi = si * invd;
        float noeff = fmaxf(invd - 1.0f, 1e-12f);
        float inoe = 1.0f / noeff;

        float u0[4] = {-1e30f, -1e30f, -1e30f, -1e30f};
        float u1[4] = {-1e30f, -1e30f, -1e30f, -1e30f};
        const float s10c = 0.31622776601683794f;
#pragma unroll
        for (int p = 0; p < 16; p++) {
            int b0 = (p >> 3) & 1, b1 = (p >> 2) & 1, b2 = (p >> 1) & 1, b3 = p & 1;
            float pr  = (float)((1 - 2 * b0) * (1 + 2 * b2)) * s10c;
            float pim = (float)((1 - 2 * b1) * (1 + 2 * b3)) * s10c;
            float dr = xhr - pr, di = xhi - pim;
            float met = -(dr * dr + di * di);
            if (b0) u1[0] = fmaxf(u1[0], met); else u0[0] = fmaxf(u0[0], met);
            if (b1) u1[1] = fmaxf(u1[1], met); else u0[1] = fmaxf(u0[1], met);
            if (b2) u1[2] = fmaxf(u1[2], met); else u0[2] = fmaxf(u0[2], met);
            if (b3) u1[3] = fmaxf(u1[3], met); else u0[3] = fmaxf(u0[3], met);
        }
        float4 out = make_float4((u0[0] - u1[0]) * inoe, (u0[1] - u1[1]) * inoe,
                                 (u0[2] - u1[2]) * inoe, (u0[3] - u1[3]) * inoe);
        *(float4*)&g_llr[(size_t)(bidx * NUE_ + c) * N_ + s * 4] = out;  // coalesced 16B
    }
}

// ---------------------------------------------------------------------------
// Decoder: one block per UE-PAIR (2 codewords, float2 lanes). Index math,
// CSR loads and shared traffic amortized 2x. CSR cached in shared.
// Parity vars (deg-1): tanh loop-invariant; their c2v never consumed.
// ---------------------------------------------------------------------------
__global__ __launch_bounds__(256)
void decode_kernel(float* __restrict__ out_bhat) {
    __shared__ float2 sL[N_];        // 8 KB
    __shared__ float2 sC[NINFOE_];   // 12 KB
    __shared__ float2 sT[NEDGE_];    // 16 KB
    __shared__ short  selist[NINFOE_];
    __shared__ short  seoff[M_ + 1];

    const int b2 = blockIdx.x;       // [0, BATCH*NUE_/2)
    const int t  = threadIdx.x;
    const float* L0 = g_llr + (size_t)(2 * b2) * N_;
    const float* L1 = L0 + N_;

    for (int n = t; n < N_; n += 256) sL[n] = make_float2(L0[n], L1[n]);
    for (int e = t; e < NINFOE_; e += 256) { sC[e] = make_float2(0.f, 0.f); selist[e] = g_elist[e]; }
    for (int m = t; m <= M_; m += 256) seoff[m] = g_eoff[m];
    __syncthreads();

    // parity-edge tanh is loop-invariant (m_vc = Lch always)
    for (int m = t; m < M_; m += 256) {
        float2 l = sL[K_ + m];
        sT[NINFOE_ + m] = make_float2(tanh_clip_half(l.x * 0.5f), tanh_clip_half(l.y * 0.5f));
    }

    for (int it = 0; it < NITER_; it++) {
        // info variables: vtot + 3 v->c messages -> tanh
        for (int n = t; n < K_; n += 256) {
            float2 c0 = sC[3 * n], c1 = sC[3 * n + 1], c2 = sC[3 * n + 2];
            float2 l = sL[n];
            float vx = l.x + c0.x + c1.x + c2.x;
            float vy = l.y + c0.y + c1.y + c2.y;
            sT[3 * n    ] = make_float2(tanh_clip_half((vx - c0.x) * 0.5f), tanh_clip_half((vy - c0.y) * 0.5f));
            sT[3 * n + 1] = make_float2(tanh_clip_half((vx - c1.x) * 0.5f), tanh_clip_half((vy - c1.y) * 0.5f));
            sT[3 * n + 2] = make_float2(tanh_clip_half((vx - c2.x) * 0.5f), tanh_clip_half((vy - c2.y) * 0.5f));
        }
        __syncthreads();
        // checks: product in ascending edge order (parity edge last), then c2v
        for (int m = t; m < M_; m += 256) {
            int o0 = seoff[m], o1 = seoff[m + 1];
            float2 p = sT[NINFOE_ + m];
            for (int q = o0; q < o1; q++) {
                float2 tt = sT[selist[q]];
                p.x *= tt.x; p.y *= tt.y;
            }
            for (int q = o0; q < o1; q++) {
                int e = selist[q];
                float2 tt = sT[e];
                sC[e] = make_float2(atanh2_acc(__fdividef(p.x, tt.x)),
                                    atanh2_acc(__fdividef(p.y, tt.y)));
            }
        }
        __syncthreads();
    }

    float* o0p = out_bhat + (size_t)(2 * b2) * K_;
    float* o1p = o0p + K_;
    for (int n = t; n < K_; n += 256) {
        float2 c0 = sC[3 * n], c1 = sC[3 * n + 1], c2 = sC[3 * n + 2];
        float2 l = sL[n];
        o0p[n] = (l.x + c0.x + c1.x + c2.x < 0.f) ? 1.0f : 0.0f;
        o1p[n] = (l.y + c0.y + c1.y + c2.y < 0.f) ? 1.0f : 0.0f;
    }
}

// ---------------------------------------------------------------------------
extern "C" void kernel_launch(void* const* d_in, const int* in_sizes, int n_in,
                              void* d_out, int out_size) {
    int shift = 10 - n_in;
    const float* ebno = (const float*)d_in[1 - shift];
    const int*   b    = (const int*)  d_in[2 - shift];
    const int*   cn   = (const int*)  d_in[4 - shift];
    const float* h_re = (const float*)d_in[6 - shift];
    const float* h_im = (const float*)d_in[7 - shift];
    const float* n_re = (const float*)d_in[8 - shift];
    const float* n_im = (const float*)d_in[9 - shift];

    float* out_bf = (float*)d_out;                       // (batch, NUE, K)
    float* out_bh = (float*)d_out + BATCH * NUE_ * K_;   // (batch, NUE, K)

    setup_count_kernel<<<1, 512>>>(cn);
    setup_place_kernel<<<(NINFOE_ + 255) / 256, 256>>>(cn);
    setup_sort_kernel<<<(M_ + 255) / 256, 256>>>();

    encode_kernel<<<BATCH * NUE_, 256>>>(b, out_bf);

    const int nr = BATCH * NSYM_;
    lmmse_kernel<<<(nr + 127) / 128, 128>>>((const float4*)h_re, (const float4*)h_im,
                                            (const float4*)n_re, (const float4*)n_im, ebno);

    decode_kernel<<<BATCH * NUE_ / 2, 256>>>(out_bh);
}